// round 1
// baseline (speedup 1.0000x reference)
#include <cuda_runtime.h>
#include <math.h>

#define CLASSN 31
#define BB 4096
#define DD 256
#define NN 8192
#define PD 32
#define KD 288          // 256 feature dims + 32 padded weight dims
#define BM 128
#define BK 8
#define TT 64           // 8192 / 128 tiles per dim
#define NTILES (TT*(TT+1)/2)   // 2080

// ---------------- device scratch (no allocs allowed) ----------------
__device__ float g_XP[NN][KD];       // [x (256) | p (32, last col 0)]
__device__ float g_sq[NN];
__device__ float g_colsum[DD];
__device__ int   g_scnt[CLASSN];
__device__ float g_tcnt[CLASSN];
__device__ int   g_tpres[CLASSN];
__device__ float g_sval[CLASSN];     // mask/c s count divisor
__device__ float g_tscl[CLASSN];     // -mask/t count divisor
__device__ float g_ge;               // log2(e)/(bw*16)
__device__ float g_invnidx;
__device__ int   g_any_odd;          // label dtype detection
__device__ float g_partial[NTILES];

__device__ __forceinline__ float ex2f(float x) {
    float y;
    asm("ex2.approx.ftz.f32 %0, %1;" : "=f"(y) : "f"(x));
    return y;
}

// ---------------- setup kernels ----------------
__global__ void k_zero() {
    int t = threadIdx.x;
    if (t < DD) g_colsum[t] = 0.f;
    if (t < CLASSN) { g_scnt[t] = 0; g_tcnt[t] = 0.f; g_tpres[t] = 0; }
    if (t == 0) g_any_odd = 0;
}

// detect whether s_label is int32 or int64: look at odd 32-bit words among
// first 4096 words (safe for both layouts). int64 -> high halves all zero.
__global__ void k_detect(const int* __restrict__ lab32) {
    int gi = blockIdx.x * blockDim.x + threadIdx.x;
    int stride = gridDim.x * blockDim.x;
    for (int w = gi; w < BB; w += stride) {
        if ((w & 1) && lab32[w] != 0) g_any_odd = 1;   // race-benign
    }
}

// copy source|target into g_XP[:, :256], compute per-row sq, column sums
__global__ void k_prep1(const float* __restrict__ src, const float* __restrict__ tgt) {
    int lane = threadIdx.x & 31;
    int wid  = threadIdx.x >> 5;
    int gw   = blockIdx.x * 8 + wid;        // 512 warps
    float cs[8];
    #pragma unroll
    for (int q = 0; q < 8; q++) cs[q] = 0.f;
    for (int r = gw; r < NN; r += 512) {
        const float* xr = (r < BB) ? (src + (size_t)r * DD)
                                   : (tgt + (size_t)(r - BB) * DD);
        float s = 0.f;
        #pragma unroll
        for (int q = 0; q < 8; q++) {
            int c = lane + 32 * q;
            float x = xr[c];
            g_XP[r][c] = x;
            s += x * x;
            cs[q] += x;
        }
        #pragma unroll
        for (int o = 16; o > 0; o >>= 1) s += __shfl_xor_sync(0xffffffffu, s, o);
        if (lane == 0) g_sq[r] = s;
    }
    #pragma unroll
    for (int q = 0; q < 8; q++) atomicAdd(&g_colsum[lane + 32 * q], cs[q]);
}

// class stats: s histogram, t column sums, t argmax presence
__global__ void k_prep2(const int* __restrict__ lab32, const float* __restrict__ tlab) {
    __shared__ int   sh_sc[CLASSN];
    __shared__ float sh_tc[CLASSN];
    __shared__ int   sh_tp[CLASSN];
    int tid = threadIdx.x;
    if (tid < CLASSN) { sh_sc[tid] = 0; sh_tc[tid] = 0.f; sh_tp[tid] = 0; }
    __syncthreads();
    int lab64 = (g_any_odd == 0);
    int gi = blockIdx.x * blockDim.x + tid;
    int stride = gridDim.x * blockDim.x;
    for (int i = gi; i < BB; i += stride) {
        int c = lab64 ? lab32[2 * i] : lab32[i];
        atomicAdd(&sh_sc[c], 1);
        const float* row = tlab + (size_t)i * CLASSN;
        float m = -1.f; int am = 0;
        #pragma unroll
        for (int c2 = 0; c2 < CLASSN; c2++) {
            float v = row[c2];
            atomicAdd(&sh_tc[c2], v);
            if (v > m) { m = v; am = c2; }
        }
        sh_tp[am] = 1;
    }
    __syncthreads();
    if (tid < CLASSN) {
        atomicAdd(&g_scnt[tid], sh_sc[tid]);
        atomicAdd(&g_tcnt[tid], sh_tc[tid]);
        if (sh_tp[tid]) g_tpres[tid] = 1;
    }
}

// derive bw/gamma, mask, n_idx, per-class scale factors
__global__ void k_prep3() {
    __shared__ float red[256];
    int tid = threadIdx.x;
    // sum of sq
    float loc = 0.f;
    for (int i = tid; i < NN; i += 256) loc += g_sq[i];
    red[tid] = loc; __syncthreads();
    for (int o = 128; o > 0; o >>= 1) { if (tid < o) red[tid] += red[tid + o]; __syncthreads(); }
    float sumsq = red[0]; __syncthreads();
    // ||colsum||^2
    float c = (tid < DD) ? g_colsum[tid] : 0.f;
    red[tid] = c * c; __syncthreads();
    for (int o = 128; o > 0; o >>= 1) { if (tid < o) red[tid] += red[tid + o]; __syncthreads(); }
    float S2 = red[0]; __syncthreads();
    // mask + per-class scales
    int m = 0;
    if (tid < CLASSN) {
        int sc = g_scnt[tid]; float tc = g_tcnt[tid]; int pr = g_tpres[tid];
        m = (sc > 0 && pr) ? 1 : 0;
        g_sval[tid] = m ? 1.f / (float)sc : 0.f;
        g_tscl[tid] = m ? -1.f / ((tc == 0.f) ? 100.f : tc) : 0.f;
    }
    red[tid] = (float)m; __syncthreads();
    for (int o = 128; o > 0; o >>= 1) { if (tid < o) red[tid] += red[tid + o]; __syncthreads(); }
    if (tid == 0) {
        float nidx = fmaxf(red[0], 1.f);
        double n = (double)NN;
        double suml2 = 2.0 * n * (double)sumsq - 2.0 * (double)S2;
        double bwraw = suml2 / (n * n - n);
        float bw = fmaxf((float)bwraw, 1e-6f) * 0.25f;   // / KERNEL_MUL^(5//2)
        g_ge = (float)(1.4426950408889634 / ((double)bw * 16.0));
        g_invnidx = 1.f / nidx;
    }
}

// fill weight columns g_XP[:, 256:288]
__global__ void k_prep4(const int* __restrict__ lab32, const float* __restrict__ tlab) {
    int idx = blockIdx.x * blockDim.x + threadIdx.x;   // NN*32 total
    int r = idx >> 5;
    int c = idx & 31;
    if (r >= NN) return;
    int lab64 = (g_any_odd == 0);
    float v = 0.f;
    if (c < CLASSN) {
        if (r < BB) {
            int lc = lab64 ? lab32[2 * r] : lab32[r];
            v = (lc == c) ? g_sval[c] : 0.f;
        } else {
            v = g_tscl[c] * tlab[(size_t)(r - BB) * CLASSN + c];
        }
    }
    g_XP[r][DD + c] = v;
}

// ---------------- main fused pairwise kernel ----------------
__global__ __launch_bounds__(256, 1) void k_main() {
    __shared__ float As[BK][BM + 4];
    __shared__ float Bs[BK][BM + 4];
    __shared__ float red[256];

    int p = blockIdx.x;
    // map p -> (bi, bj), bi <= bj, upper-triangle tiles
    float tf = (float)TT + 0.5f;
    int bi = (int)(tf - sqrtf(tf * tf - 2.0f * (float)p));
    while (bi > 0 && (bi * TT - bi * (bi - 1) / 2) > p) bi--;
    while (((bi + 1) * TT - (bi + 1) * bi / 2) <= p) bi++;
    int bj = bi + (p - (bi * TT - bi * (bi - 1) / 2));

    int tid = threadIdx.x;
    int tx = tid & 15, ty = tid >> 4;
    int rowA0 = bi * BM, rowB0 = bj * BM;
    int lrow = tid >> 1, lhalf = tid & 1;

    float accX[8][8], accW[8][8];
    #pragma unroll
    for (int i = 0; i < 8; i++)
        #pragma unroll
        for (int j = 0; j < 8; j++) { accX[i][j] = 0.f; accW[i][j] = 0.f; }

    const float* pa = &g_XP[rowA0 + lrow][0];
    const float* pb = &g_XP[rowB0 + lrow][0];

    // phase 1: 256 feature dims -> accX (dot products)
    for (int kk = 0; kk < DD; kk += BK) {
        float4 va = *(const float4*)(pa + kk + lhalf * 4);
        float4 vb = *(const float4*)(pb + kk + lhalf * 4);
        __syncthreads();
        As[lhalf * 4 + 0][lrow] = va.x; As[lhalf * 4 + 1][lrow] = va.y;
        As[lhalf * 4 + 2][lrow] = va.z; As[lhalf * 4 + 3][lrow] = va.w;
        Bs[lhalf * 4 + 0][lrow] = vb.x; Bs[lhalf * 4 + 1][lrow] = vb.y;
        Bs[lhalf * 4 + 2][lrow] = vb.z; Bs[lhalf * 4 + 3][lrow] = vb.w;
        __syncthreads();
        #pragma unroll
        for (int k = 0; k < BK; k++) {
            float a[8], b[8];
            #pragma unroll
            for (int i = 0; i < 8; i++) a[i] = As[k][ty * 8 + i];
            #pragma unroll
            for (int j = 0; j < 8; j++) b[j] = Bs[k][tx * 8 + j];
            #pragma unroll
            for (int i = 0; i < 8; i++)
                #pragma unroll
                for (int j = 0; j < 8; j++)
                    accX[i][j] = fmaf(a[i], b[j], accX[i][j]);
        }
    }
    // phase 2: 32 weight dims -> accW (rank-31 pair weights)
    for (int kk = DD; kk < KD; kk += BK) {
        float4 va = *(const float4*)(pa + kk + lhalf * 4);
        float4 vb = *(const float4*)(pb + kk + lhalf * 4);
        __syncthreads();
        As[lhalf * 4 + 0][lrow] = va.x; As[lhalf * 4 + 1][lrow] = va.y;
        As[lhalf * 4 + 2][lrow] = va.z; As[lhalf * 4 + 3][lrow] = va.w;
        Bs[lhalf * 4 + 0][lrow] = vb.x; Bs[lhalf * 4 + 1][lrow] = vb.y;
        Bs[lhalf * 4 + 2][lrow] = vb.z; Bs[lhalf * 4 + 3][lrow] = vb.w;
        __syncthreads();
        #pragma unroll
        for (int k = 0; k < BK; k++) {
            float a[8], b[8];
            #pragma unroll
            for (int i = 0; i < 8; i++) a[i] = As[k][ty * 8 + i];
            #pragma unroll
            for (int j = 0; j < 8; j++) b[j] = Bs[k][tx * 8 + j];
            #pragma unroll
            for (int i = 0; i < 8; i++)
                #pragma unroll
                for (int j = 0; j < 8; j++)
                    accW[i][j] = fmaf(a[i], b[j], accW[i][j]);
        }
    }

    // epilogue: l2 -> K (5 gaussians from one exp) -> weighted sum
    float sqA[8], sqB[8];
    #pragma unroll
    for (int i = 0; i < 8; i++) sqA[i] = g_sq[rowA0 + ty * 8 + i];
    #pragma unroll
    for (int j = 0; j < 8; j++) sqB[j] = g_sq[rowB0 + tx * 8 + j];
    float ge = g_ge;
    bool diag = (bi == bj);
    float loc = 0.f;
    #pragma unroll
    for (int i = 0; i < 8; i++) {
        #pragma unroll
        for (int j = 0; j < 8; j++) {
            float l2 = fmaxf(sqA[i] + sqB[j] - 2.f * accX[i][j], 0.f);
            float z = ex2f(-l2 * ge);          // exp(-l2/(16*bw))
            float z2 = z * z, z4 = z2 * z2, z8 = z4 * z4;
            float Kv = z * (1.f + z) + z4 + z8 + z8 * z8;  // z+z^2+z^4+z^8+z^16
            float f = 2.f;
            if (diag) {
                int ra = ty * 8 + i, rb = tx * 8 + j;
                f = (ra < rb) ? 2.f : ((ra == rb) ? 1.f : 0.f);
            }
            loc += f * Kv * accW[i][j];
        }
    }
    red[tid] = loc; __syncthreads();
    for (int o = 128; o > 0; o >>= 1) { if (tid < o) red[tid] += red[tid + o]; __syncthreads(); }
    if (tid == 0) g_partial[p] = red[0];
}

__global__ void k_final(float* out) {
    __shared__ float red[256];
    int tid = threadIdx.x;
    float loc = 0.f;
    for (int i = tid; i < NTILES; i += 256) loc += g_partial[i];
    red[tid] = loc; __syncthreads();
    for (int o = 128; o > 0; o >>= 1) { if (tid < o) red[tid] += red[tid + o]; __syncthreads(); }
    if (tid == 0) out[0] = red[0] * g_invnidx;
}

// ---------------- entry ----------------
extern "C" void kernel_launch(void* const* d_in, const int* in_sizes, int n_in,
                              void* d_out, int out_size) {
    const float* src  = (const float*)d_in[0];
    const float* tgt  = (const float*)d_in[1];
    const int*   slab = (const int*)d_in[2];   // int32 or int64 (detected)
    const float* tlab = (const float*)d_in[3];
    float* out = (float*)d_out;

    k_zero  <<<1, 256>>>();
    k_detect<<<8, 256>>>(slab);
    k_prep1 <<<64, 256>>>(src, tgt);
    k_prep2 <<<32, 256>>>(slab, tlab);
    k_prep3 <<<1, 256>>>();
    k_prep4 <<<(NN * 32) / 256, 256>>>(slab, tlab);
    k_main  <<<NTILES, 256>>>();
    k_final <<<1, 256>>>(out);
}

// round 5
// speedup vs baseline: 1.1457x; 1.1457x over previous
#include <cuda_runtime.h>
#include <math.h>

#define CLASSN 31
#define BB 4096
#define DD 256
#define NN 8192
#define PD 32
#define KD 288          // 256 feature dims + 32 padded weight dims
#define BM 128
#define BK 8
#define TT 64           // 8192 / 128 tiles per dim
#define NTILES (TT*(TT+1)/2)   // 2080

// ---------------- device scratch (no allocs allowed) ----------------
__device__ float g_XP[NN][KD];       // [x (256) | p (32, last col 0)]
__device__ float g_sq[NN];
__device__ float g_colsum[DD];
__device__ int   g_scnt[CLASSN];
__device__ float g_tcnt[CLASSN];
__device__ int   g_tpres[CLASSN];
__device__ float g_sval[CLASSN];     // mask/s count divisor
__device__ float g_tscl[CLASSN];     // -mask/t count divisor
__device__ float g_ge;               // log2(e)/(bw*16)
__device__ float g_invnidx;
__device__ int   g_any_odd;          // label dtype detection
__device__ float g_partial[NTILES];

__device__ __forceinline__ float ex2f(float x) {
    float y;
    asm("ex2.approx.ftz.f32 %0, %1;" : "=f"(y) : "f"(x));
    return y;
}

// packed fp32x2 FMA (FFMA2) — 2 fp32 FMAs per instruction on sm_103a
#define FFMA2(acc, a, b) \
    asm("fma.rn.f32x2 %0, %1, %2, %0;" : "+l"(acc) : "l"(a), "l"(b))
#define PACK2(d, f) \
    asm("mov.b64 %0, {%1, %1};" : "=l"(d) : "f"(f))
#define UNPACK2(lo, hi, s) \
    asm("mov.b64 {%0, %1}, %2;" : "=f"(lo), "=f"(hi) : "l"(s))

// ---------------- setup kernels ----------------
__global__ void k_zero() {
    int t = threadIdx.x;
    if (t < DD) g_colsum[t] = 0.f;
    if (t < CLASSN) { g_scnt[t] = 0; g_tcnt[t] = 0.f; g_tpres[t] = 0; }
    if (t == 0) g_any_odd = 0;
}

// detect whether s_label is int32 or int64 (int64 -> odd 32-bit words all zero)
__global__ void k_detect(const int* __restrict__ lab32) {
    int gi = blockIdx.x * blockDim.x + threadIdx.x;
    int stride = gridDim.x * blockDim.x;
    for (int w = gi; w < BB; w += stride) {
        if ((w & 1) && lab32[w] != 0) g_any_odd = 1;   // race-benign
    }
}

// copy source|target into g_XP[:, :256], compute per-row sq, column sums
__global__ void k_prep1(const float* __restrict__ src, const float* __restrict__ tgt) {
    int lane = threadIdx.x & 31;
    int wid  = threadIdx.x >> 5;
    int gw   = blockIdx.x * 8 + wid;        // 512 warps
    float cs[8];
    #pragma unroll
    for (int q = 0; q < 8; q++) cs[q] = 0.f;
    for (int r = gw; r < NN; r += 512) {
        const float* xr = (r < BB) ? (src + (size_t)r * DD)
                                   : (tgt + (size_t)(r - BB) * DD);
        float s = 0.f;
        #pragma unroll
        for (int q = 0; q < 8; q++) {
            int c = lane + 32 * q;
            float x = xr[c];
            g_XP[r][c] = x;
            s += x * x;
            cs[q] += x;
        }
        #pragma unroll
        for (int o = 16; o > 0; o >>= 1) s += __shfl_xor_sync(0xffffffffu, s, o);
        if (lane == 0) g_sq[r] = s;
    }
    #pragma unroll
    for (int q = 0; q < 8; q++) atomicAdd(&g_colsum[lane + 32 * q], cs[q]);
}

// class stats, warp-per-row: lane c owns class c. Coalesced reads, zero
// same-address shared-atomic serialization (was 98.8us in round 1).
__global__ void k_prep2(const int* __restrict__ lab32, const float* __restrict__ tlab) {
    __shared__ int sh_sc[CLASSN];
    int tid = threadIdx.x;
    int lane = tid & 31;
    if (tid < CLASSN) sh_sc[tid] = 0;
    __syncthreads();
    int lab64 = (g_any_odd == 0);
    int gwarp = (blockIdx.x * blockDim.x + tid) >> 5;   // 0..127
    float tc = 0.f;
    int pres = 0;
    for (int r = gwarp; r < BB; r += 128) {
        float v = (lane < CLASSN) ? tlab[(size_t)r * CLASSN + lane] : -1e30f;
        if (lane < CLASSN) tc += v;
        float m = v;
        #pragma unroll
        for (int o = 16; o > 0; o >>= 1) m = fmaxf(m, __shfl_xor_sync(0xffffffffu, m, o));
        unsigned bal = __ballot_sync(0xffffffffu, v == m);
        int am = __ffs(bal) - 1;                        // first max = jnp.argmax
        if (lane == am) pres = 1;
        if (lane == 0) {
            int c = lab64 ? lab32[2 * r] : lab32[r];
            atomicAdd(&sh_sc[c], 1);
        }
    }
    if (lane < CLASSN) {
        atomicAdd(&g_tcnt[lane], tc);
        if (pres) g_tpres[lane] = 1;
    }
    __syncthreads();
    if (tid < CLASSN) atomicAdd(&g_scnt[tid], sh_sc[tid]);
}

// derive bw/gamma, mask, n_idx, per-class scale factors
__global__ void k_prep3() {
    __shared__ float red[256];
    int tid = threadIdx.x;
    float loc = 0.f;
    for (int i = tid; i < NN; i += 256) loc += g_sq[i];
    red[tid] = loc; __syncthreads();
    for (int o = 128; o > 0; o >>= 1) { if (tid < o) red[tid] += red[tid + o]; __syncthreads(); }
    float sumsq = red[0]; __syncthreads();
    float c = (tid < DD) ? g_colsum[tid] : 0.f;
    red[tid] = c * c; __syncthreads();
    for (int o = 128; o > 0; o >>= 1) { if (tid < o) red[tid] += red[tid + o]; __syncthreads(); }
    float S2 = red[0]; __syncthreads();
    int m = 0;
    if (tid < CLASSN) {
        int sc = g_scnt[tid]; float tc = g_tcnt[tid]; int pr = g_tpres[tid];
        m = (sc > 0 && pr) ? 1 : 0;
        g_sval[tid] = m ? 1.f / (float)sc : 0.f;
        g_tscl[tid] = m ? -1.f / ((tc == 0.f) ? 100.f : tc) : 0.f;
    }
    red[tid] = (float)m; __syncthreads();
    for (int o = 128; o > 0; o >>= 1) { if (tid < o) red[tid] += red[tid + o]; __syncthreads(); }
    if (tid == 0) {
        float nidx = fmaxf(red[0], 1.f);
        double n = (double)NN;
        double suml2 = 2.0 * n * (double)sumsq - 2.0 * (double)S2;
        double bwraw = suml2 / (n * n - n);
        float bw = fmaxf((float)bwraw, 1e-6f) * 0.25f;   // / KERNEL_MUL^(5//2)
        g_ge = (float)(1.4426950408889634 / ((double)bw * 16.0));
        g_invnidx = 1.f / nidx;
    }
}

// fill weight columns g_XP[:, 256:288]
__global__ void k_prep4(const int* __restrict__ lab32, const float* __restrict__ tlab) {
    int idx = blockIdx.x * blockDim.x + threadIdx.x;   // NN*32 total
    int r = idx >> 5;
    int c = idx & 31;
    if (r >= NN) return;
    int lab64 = (g_any_odd == 0);
    float v = 0.f;
    if (c < CLASSN) {
        if (r < BB) {
            int lc = lab64 ? lab32[2 * r] : lab32[r];
            v = (lc == c) ? g_sval[c] : 0.f;
        } else {
            v = g_tscl[c] * tlab[(size_t)(r - BB) * CLASSN + c];
        }
    }
    g_XP[r][DD + c] = v;
}

// ---------------- main fused pairwise kernel (FFMA2 mainloop) ----------------
__global__ __launch_bounds__(256, 1) void k_main() {
    __shared__ float As[BK][BM + 4];
    __shared__ float Bs[BK][BM + 4];
    __shared__ float red[256];

    int p = blockIdx.x;
    // map p -> (bi, bj), bi <= bj, upper-triangle tiles
    float tf = (float)TT + 0.5f;
    int bi = (int)(tf - sqrtf(tf * tf - 2.0f * (float)p));
    while (bi > 0 && (bi * TT - bi * (bi - 1) / 2) > p) bi--;
    while (((bi + 1) * TT - (bi + 1) * bi / 2) <= p) bi++;
    int bj = bi + (p - (bi * TT - bi * (bi - 1) / 2));

    int tid = threadIdx.x;
    int tx = tid & 15, ty = tid >> 4;
    int rowA0 = bi * BM, rowB0 = bj * BM;
    int lrow = tid >> 1, lhalf = tid & 1;

    unsigned long long accX[8][4], accW[8][4];
    #pragma unroll
    for (int i = 0; i < 8; i++)
        #pragma unroll
        for (int j = 0; j < 4; j++) { accX[i][j] = 0ull; accW[i][j] = 0ull; }

    const float* pa = &g_XP[rowA0 + lrow][0];
    const float* pb = &g_XP[rowB0 + lrow][0];

    // phase 1: 256 feature dims -> accX (dot products)
    for (int kk = 0; kk < DD; kk += BK) {
        float4 va = *(const float4*)(pa + kk + lhalf * 4);
        float4 vb = *(const float4*)(pb + kk + lhalf * 4);
        __syncthreads();
        As[lhalf * 4 + 0][lrow] = va.x; As[lhalf * 4 + 1][lrow] = va.y;
        As[lhalf * 4 + 2][lrow] = va.z; As[lhalf * 4 + 3][lrow] = va.w;
        Bs[lhalf * 4 + 0][lrow] = vb.x; Bs[lhalf * 4 + 1][lrow] = vb.y;
        Bs[lhalf * 4 + 2][lrow] = vb.z; Bs[lhalf * 4 + 3][lrow] = vb.w;
        __syncthreads();
        #pragma unroll
        for (int k = 0; k < BK; k++) {
            float4 af0 = *(const float4*)&As[k][ty * 8];
            float4 af1 = *(const float4*)&As[k][ty * 8 + 4];
            unsigned long long a2[8], b2[4];
            PACK2(a2[0], af0.x); PACK2(a2[1], af0.y);
            PACK2(a2[2], af0.z); PACK2(a2[3], af0.w);
            PACK2(a2[4], af1.x); PACK2(a2[5], af1.y);
            PACK2(a2[6], af1.z); PACK2(a2[7], af1.w);
            #pragma unroll
            for (int jp = 0; jp < 4; jp++)
                b2[jp] = *(const unsigned long long*)&Bs[k][tx * 8 + 2 * jp];
            #pragma unroll
            for (int i = 0; i < 8; i++)
                #pragma unroll
                for (int jp = 0; jp < 4; jp++)
                    FFMA2(accX[i][jp], a2[i], b2[jp]);
        }
    }
    // phase 2: 32 weight dims -> accW (rank-31 pair weights)
    for (int kk = DD; kk < KD; kk += BK) {
        float4 va = *(const float4*)(pa + kk + lhalf * 4);
        float4 vb = *(const float4*)(pb + kk + lhalf * 4);
        __syncthreads();
        As[lhalf * 4 + 0][lrow] = va.x; As[lhalf * 4 + 1][lrow] = va.y;
        As[lhalf * 4 + 2][lrow] = va.z; As[lhalf * 4 + 3][lrow] = va.w;
        Bs[lhalf * 4 + 0][lrow] = vb.x; Bs[lhalf * 4 + 1][lrow] = vb.y;
        Bs[lhalf * 4 + 2][lrow] = vb.z; Bs[lhalf * 4 + 3][lrow] = vb.w;
        __syncthreads();
        #pragma unroll
        for (int k = 0; k < BK; k++) {
            float4 af0 = *(const float4*)&As[k][ty * 8];
            float4 af1 = *(const float4*)&As[k][ty * 8 + 4];
            unsigned long long a2[8], b2[4];
            PACK2(a2[0], af0.x); PACK2(a2[1], af0.y);
            PACK2(a2[2], af0.z); PACK2(a2[3], af0.w);
            PACK2(a2[4], af1.x); PACK2(a2[5], af1.y);
            PACK2(a2[6], af1.z); PACK2(a2[7], af1.w);
            #pragma unroll
            for (int jp = 0; jp < 4; jp++)
                b2[jp] = *(const unsigned long long*)&Bs[k][tx * 8 + 2 * jp];
            #pragma unroll
            for (int i = 0; i < 8; i++)
                #pragma unroll
                for (int jp = 0; jp < 4; jp++)
                    FFMA2(accW[i][jp], a2[i], b2[jp]);
        }
    }

    // epilogue: l2 -> K (5 gaussians from one exp) -> weighted sum
    float sqA[8], sqB[8];
    #pragma unroll
    for (int i = 0; i < 8; i++) sqA[i] = g_sq[rowA0 + ty * 8 + i];
    #pragma unroll
    for (int j = 0; j < 8; j++) sqB[j] = g_sq[rowB0 + tx * 8 + j];
    float ge = g_ge;
    bool diag = (bi == bj);
    float loc = 0.f;
    #pragma unroll
    for (int i = 0; i < 8; i++) {
        #pragma unroll
        for (int jp = 0; jp < 4; jp++) {
            float x0, x1, w0, w1;
            UNPACK2(x0, x1, accX[i][jp]);
            UNPACK2(w0, w1, accW[i][jp]);
            #pragma unroll
            for (int h = 0; h < 2; h++) {
                int j = 2 * jp + h;
                float xv = h ? x1 : x0;
                float wv = h ? w1 : w0;
                float l2 = fmaxf(sqA[i] + sqB[j] - 2.f * xv, 0.f);
                float z = ex2f(-l2 * ge);          // exp(-l2/(16*bw))
                float z2 = z * z, z4 = z2 * z2, z8 = z4 * z4;
                float Kv = z * (1.f + z) + z4 + z8 + z8 * z8;  // z+z^2+z^4+z^8+z^16
                float f = 2.f;
                if (diag) {
                    int ra = ty * 8 + i, rb = tx * 8 + j;
                    f = (ra < rb) ? 2.f : ((ra == rb) ? 1.f : 0.f);
                }
                loc += f * Kv * wv;
            }
        }
    }
    red[tid] = loc; __syncthreads();
    for (int o = 128; o > 0; o >>= 1) { if (tid < o) red[tid] += red[tid + o]; __syncthreads(); }
    if (tid == 0) g_partial[p] = red[0];
}

__global__ void k_final(float* out) {
    __shared__ float red[256];
    int tid = threadIdx.x;
    float loc = 0.f;
    for (int i = tid; i < NTILES; i += 256) loc += g_partial[i];
    red[tid] = loc; __syncthreads();
    for (int o = 128; o > 0; o >>= 1) { if (tid < o) red[tid] += red[tid + o]; __syncthreads(); }
    if (tid == 0) out[0] = red[0] * g_invnidx;
}

// ---------------- entry ----------------
extern "C" void kernel_launch(void* const* d_in, const int* in_sizes, int n_in,
                              void* d_out, int out_size) {
    const float* src  = (const float*)d_in[0];
    const float* tgt  = (const float*)d_in[1];
    const int*   slab = (const int*)d_in[2];   // int32 or int64 (detected)
    const float* tlab = (const float*)d_in[3];
    float* out = (float*)d_out;

    k_zero  <<<1, 256>>>();
    k_detect<<<8, 256>>>(slab);
    k_prep1 <<<64, 256>>>(src, tgt);
    k_prep2 <<<16, 256>>>(slab, tlab);
    k_prep3 <<<1, 256>>>();
    k_prep4 <<<(NN * 32) / 256, 256>>>(slab, tlab);
    k_main  <<<NTILES, 256>>>();
    k_final <<<1, 256>>>(out);
}